// round 17
// baseline (speedup 1.0000x reference)
#include <cuda_runtime.h>
#include <cstdint>

// MetaUpscale: x (2,64,128,128) f32, lw (256,256,576,3) f32, scale=2
// out (2,3,256,256) f32
// out[n,ch,oh,ow] = sum_{c9} patch[n, oh/2, ow/2, c9] * lw[oh,ow,c9,ch]
//
// R16: lw streamed via cp.async (LDGSTS) into a per-warp 2-stage smem ring.
// MLP is decoupled from registers (whole commit-groups stay in flight while
// the warp computes), and the consumer reads lw back in the R5 layout (lane
// owns 12 consecutive elements, stride-3 LDS.128, conflict-free) -> channel
// map is compile-time: no selects, no phase remap. Warp = one lw row segment
// (3456 floats = both subpixels of one output row).

#define HH_   128
#define WW_   128
#define CC_   64
#define C9_   576
#define OHW   256
#define LWPIX 1728
#define PIX_PER_BLK 8
#define PSTR  580            // padded floats per pixel in prep (f4-aligned, bank-spread)
#define STAGE_F4 96          // float4 per stage (one superiter: 384 elements)
#define NSTAGE 2

#define SMEM_STAGE_BYTES (16 * NSTAGE * STAGE_F4 * 16)   // 49152
#define SMEM_P0 SMEM_STAGE_BYTES
#define SMEM_P0_BYTES (PIX_PER_BLK * PSTR * 4)           // 18560
#define SMEM_P1 (SMEM_P0 + SMEM_P0_BYTES)
#define SMEM_TOTAL (SMEM_P1 + SMEM_P0_BYTES)             // 86272

__device__ __forceinline__ void cpa16(uint32_t dst, const void* src) {
    asm volatile("cp.async.cg.shared.global [%0], [%1], 16;"
                 :: "r"(dst), "l"(src) : "memory");
}
#define CPA_COMMIT() asm volatile("cp.async.commit_group;" ::: "memory")
#define CPA_WAIT(n)  asm volatile("cp.async.wait_group %0;" :: "n"(n) : "memory")

// Issue superiter t's 3 LDGSTS.128 into ring slot s (one commit group).
#define ISSUE(s, t)                                                      \
    do {                                                                 \
        const uint32_t d = stage_u32 + (s) * (STAGE_F4 * 16) + L * 16;   \
        const float4* g = row + 96 * (t) + L;                            \
        cpa16(d,        g);                                              \
        cpa16(d + 512,  g + 32);                                         \
        cpa16(d + 1024, g + 64);                                         \
        CPA_COMMIT();                                                    \
    } while (0)

// Accumulate 12 elements (v0,v1,v2) vs patch float4 P into acc[S][b][*].
// Element k (0..11): channel k%3, patch component k/3.
#define ACCB(S, b, P)                                                    \
    do {                                                                 \
        acc[S][b][0] += v0.x * P.x;                                      \
        acc[S][b][1] += v0.y * P.x;                                      \
        acc[S][b][2] += v0.z * P.x;                                      \
        acc[S][b][0] += v0.w * P.y;                                      \
        acc[S][b][1] += v1.x * P.y;                                      \
        acc[S][b][2] += v1.y * P.y;                                      \
        acc[S][b][0] += v1.z * P.z;                                      \
        acc[S][b][1] += v1.w * P.z;                                      \
        acc[S][b][2] += v2.x * P.z;                                      \
        acc[S][b][0] += v2.y * P.w;                                      \
        acc[S][b][1] += v2.z * P.w;                                      \
        acc[S][b][2] += v2.w * P.w;                                      \
    } while (0)

// Consume superiter t from ring slot s (t != 4). POFF: patch f4 offset
// (0 sub0, 144 sub1). S: subpixel accumulator slot.
#define CONSUME(t, s, POFF, S)                                           \
    do {                                                                 \
        const float4* st = stageW + (s) * STAGE_F4 + 3 * L;              \
        const float4 v0 = st[0];                                         \
        const float4 v1 = st[1];                                         \
        const float4 v2 = st[2];                                         \
        const float4 P0 = pr0[L + 32 * (t) - (POFF)];                    \
        const float4 P1 = pr1[L + 32 * (t) - (POFF)];                    \
        ACCB(S, 0, P0);                                                  \
        ACCB(S, 1, P1);                                                  \
    } while (0)

__global__ __launch_bounds__(512, 2)
void meta_upscale_kernel(const float* __restrict__ x,
                         const float* __restrict__ lw,
                         float* __restrict__ out)
{
    extern __shared__ char smem[];

    const int bid = blockIdx.x;          // 2048 = 128 rows x 16 groups of 8 px
    const int hh  = bid >> 4;
    const int gw  = bid & 15;
    const int ww_base = gw * PIX_PER_BLK;
    const int tid = threadIdx.x;

    const int w    = tid >> 5;           // 16 warps: (pix, output row a)
    const int L    = tid & 31;
    const int pix  = w >> 1;
    const int a    = w & 1;
    const int ww   = ww_base + pix;
    const int oh0  = 2 * hh;
    const int ow0  = 2 * ww;

    const float4* __restrict__ row =
        (const float4*)(lw + ((size_t)(oh0 + a) * OHW + ow0) * LWPIX); // 864 f4

    float4* stageW = (float4*)(smem + w * (NSTAGE * STAGE_F4 * 16));
    const uint32_t stage_u32 = (uint32_t)__cvta_generic_to_shared(stageW);

    float* prep0f = (float*)(smem + SMEM_P0);
    float* prep1f = (float*)(smem + SMEM_P1);
    const float4* pr0 = (const float4*)(prep0f + PSTR * pix);
    const float4* pr1 = (const float4*)(prep1f + PSTR * pix);

    // Prime the ring BEFORE the prep build: both stages' LDGSTS fly during
    // the x gather + barrier (they touch only gmem + the stage region).
    ISSUE(0, 0);
    ISSUE(1, 1);

    // ------------- prep build: coalesced x reads, scatter to <=3 slots ------
    // idx enumerates (b, c, kh, u), u = 10 consecutive x columns.
    for (int idx = tid; idx < 2 * CC_ * 3 * 10; idx += 512) {
        const int rowi = idx / 10;
        const int u    = idx - 10 * rowi;
        const int b    = rowi / 192;
        const int rem  = rowi - 192 * b;
        const int c    = rem / 3;
        const int kh   = rem - 3 * c;
        const int y    = hh + kh - 1;
        const int xc   = ww_base + u - 1;
        float xv = 0.0f;
        if ((unsigned)y < HH_ && (unsigned)xc < WW_)
            xv = __ldg(x + ((b * CC_ + c) * HH_ + y) * WW_ + xc);
        float* dst = b ? prep1f : prep0f;
        const int c9b = c * 9 + kh * 3;
        #pragma unroll
        for (int kw = 0; kw < 3; kw++) {
            const int px = u - kw;
            if ((unsigned)px < PIX_PER_BLK)
                dst[px * PSTR + c9b + kw] = xv;
        }
    }
    __syncthreads();

    float acc[2][2][3];                  // [sub][batch][channel]
    #pragma unroll
    for (int s = 0; s < 2; s++)
        #pragma unroll
        for (int b = 0; b < 2; b++) {
            acc[s][b][0] = 0.f; acc[s][b][1] = 0.f; acc[s][b][2] = 0.f;
        }

    // 9 superiters x 384 elements = 3456 (both subpixels; boundary at
    // element 1728 = t=4, lane 16). Ring: wait(<=1), consume t, issue t+2.
    CPA_WAIT(1);  CONSUME(0, 0, 0, 0);    ISSUE(0, 2);
    CPA_WAIT(1);  CONSUME(1, 1, 0, 0);    ISSUE(1, 3);
    CPA_WAIT(1);  CONSUME(2, 0, 0, 0);    ISSUE(0, 4);
    CPA_WAIT(1);  CONSUME(3, 1, 0, 0);    ISSUE(1, 5);

    CPA_WAIT(1);
    {   // t = 4 boundary: lanes 0-15 sub0, lanes 16-31 sub1 (patch -144 f4)
        const float4* st = stageW + 0 * STAGE_F4 + 3 * L;
        const float4 v0 = st[0];
        const float4 v1 = st[1];
        const float4 v2 = st[2];
        const int pidx = L + 128 - ((L >= 16) ? 144 : 0);
        const float4 P0 = pr0[pidx];
        const float4 P1 = pr1[pidx];
        if (L < 16) { ACCB(0, 0, P0); ACCB(0, 1, P1); }
        else        { ACCB(1, 0, P0); ACCB(1, 1, P1); }
    }
    ISSUE(0, 6);

    CPA_WAIT(1);  CONSUME(5, 1, 144, 1);  ISSUE(1, 7);
    CPA_WAIT(1);  CONSUME(6, 0, 144, 1);  ISSUE(0, 8);
    CPA_WAIT(1);  CONSUME(7, 1, 144, 1);
    CPA_WAIT(0);  CONSUME(8, 0, 144, 1);

    // ------------- warp butterfly reduction (12 values) ----------------------
    #pragma unroll
    for (int d = 16; d > 0; d >>= 1) {
        #pragma unroll
        for (int s = 0; s < 2; s++)
            #pragma unroll
            for (int b = 0; b < 2; b++) {
                acc[s][b][0] += __shfl_xor_sync(0xFFFFFFFFu, acc[s][b][0], d);
                acc[s][b][1] += __shfl_xor_sync(0xFFFFFFFFu, acc[s][b][1], d);
                acc[s][b][2] += __shfl_xor_sync(0xFFFFFFFFu, acc[s][b][2], d);
            }
    }

    if (L == 0) {
        #pragma unroll
        for (int s = 0; s < 2; s++) {
            const int p = (oh0 + a) * OHW + (ow0 + s);
            #pragma unroll
            for (int b = 0; b < 2; b++) {
                out[(b * 3 + 0) * OHW * OHW + p] = acc[s][b][0];
                out[(b * 3 + 1) * OHW * OHW + p] = acc[s][b][1];
                out[(b * 3 + 2) * OHW * OHW + p] = acc[s][b][2];
            }
        }
    }
}

extern "C" void kernel_launch(void* const* d_in, const int* in_sizes, int n_in,
                              void* d_out, int out_size)
{
    const float* x  = (const float*)d_in[0];   // (2,64,128,128) f32
    const float* lw = (const float*)d_in[1];   // (256,256,576,3) f32
    float* out = (float*)d_out;                // (2,3,256,256) f32

    // 86.3 KB dynamic smem: opt-in above the 48 KB default (idempotent,
    // host-side attribute set; no allocation).
    cudaFuncSetAttribute(meta_upscale_kernel,
                         cudaFuncAttributeMaxDynamicSharedMemorySize,
                         SMEM_TOTAL);

    // 128 rows x 16 groups of 8 pixels; 512 threads = 16 warps, 2 blocks/SM
    meta_upscale_kernel<<<128 * 16, 512, SMEM_TOTAL>>>(x, lw, out);
}